// round 16
// baseline (speedup 1.0000x reference)
#include <cuda_runtime.h>
#include <cuda_bf16.h>

#define NN 512
#define BATCH 32
#define TT 4
#define NROWS (BATCH * TT)                        // 128
#define SRC_ELEMS ((size_t)BATCH * 2 * NN * NN)   // 16,777,216
#define TGT_ELEMS ((size_t)NROWS * NN)            // 65,536

// FFT results (pre-scaled by cbrt(0.25)), SoA. Allocation-free scratch.
__device__ float g_Yr[NROWS][NN];
__device__ float g_Yi[NROWS][NN];

typedef unsigned long long u64;

// ---- packed f32x2 helpers ----
__device__ __forceinline__ u64 pk2(float lo, float hi) {
    u64 r; asm("mov.b64 %0, {%1, %2};" : "=l"(r) : "f"(lo), "f"(hi)); return r;
}
__device__ __forceinline__ void up2(u64 v, float& lo, float& hi) {
    asm("mov.b64 {%0, %1}, %2;" : "=f"(lo), "=f"(hi) : "l"(v));
}
__device__ __forceinline__ u64 f2mul(u64 a, u64 b) {
    u64 d; asm("mul.rn.f32x2 %0, %1, %2;" : "=l"(d) : "l"(a), "l"(b)); return d;
}
__device__ __forceinline__ u64 f2fma(u64 a, u64 b, u64 c) {
    u64 d; asm("fma.rn.f32x2 %0, %1, %2, %3;" : "=l"(d) : "l"(a), "l"(b), "l"(c)); return d;
}

#define SGNMASK 0x8000000080000000ULL

// bank swizzle (bijective): j -> j XOR (4 * ((j>>5)&1)).
__device__ __forceinline__ int swz(int j) { return j ^ ((j >> 3) & 4); }

// ---------------------------------------------------------------------------
// Kernel 1: 512-pt DFT of real input, per row (b,t). Output pre-scaled by
// cbrt(0.25) so the bispectrum triple product carries 1/T = 0.25 exactly.
// ---------------------------------------------------------------------------
__global__ __launch_bounds__(1024) void dft512_kernel(const float* __restrict__ x) {
    __shared__ float xs[NN];
    __shared__ float s[NN / 2];
    __shared__ float d[NN / 2];
    __shared__ float pRe[3][256];
    __shared__ float pIm[3][256];
    __shared__ float pAlt[4];

    const int row = blockIdx.x;
    const int tid = threadIdx.x;
    const int k   = tid & 255;
    const int q   = tid >> 8;

    if (tid < NN) xs[tid] = x[row * NN + tid];
    __syncthreads();
    if (tid >= 1 && tid < 256) {
        s[tid] = xs[tid] + xs[NN - tid];
        d[tid] = xs[tid] - xs[NN - tid];
    }
    __syncthreads();

    const float W = 6.283185307179586f / (float)NN;
    float s2, c2;
    sincosf(2.0f * W * (float)k, &s2, &c2);

    float re = 0.0f, im = 0.0f, alt = 0.0f;

#pragma unroll
    for (int c = 0; c < 2; ++c) {
        const int n0  = q * 64 + c * 32;
        const int phA = (k * n0) & (NN - 1);
        const int phB = (k * (n0 + 1)) & (NN - 1);
        float sA, cA, sB, cB;
        sincosf(W * (float)phA, &sA, &cA);
        sincosf(W * (float)phB, &sB, &cB);
#pragma unroll
        for (int j = 0; j < 16; ++j) {
            const int nA = n0 + 2 * j;
            const int nB = nA + 1;
            if (nA >= 1) {
                re  = fmaf(s[nA], cA, re);
                im  = fmaf(-d[nA], sA, im);
                alt += s[nA];
            }
            re  = fmaf(s[nB], cB, re);
            im  = fmaf(-d[nB], sB, im);
            alt -= s[nB];
            const float nrA = fmaf(cA, c2, -(sA * s2));
            sA = fmaf(cA, s2, sA * c2); cA = nrA;
            const float nrB = fmaf(cB, c2, -(sB * s2));
            sB = fmaf(cB, s2, sB * c2); cB = nrB;
        }
    }

    if (q > 0) {
        pRe[q - 1][k] = re;
        pIm[q - 1][k] = im;
        if (k == 0) pAlt[q] = alt;
    } else if (k == 0) {
        pAlt[0] = alt;
    }
    __syncthreads();

    if (q == 0) {
        const float SC = 0.6299605249474366f;   // cbrt(0.25)
        re += pRe[0][k] + pRe[1][k] + pRe[2][k];
        im += pIm[0][k] + pIm[1][k] + pIm[2][k];
        const float x0 = xs[0], x256 = xs[NN / 2];
        re += x0 + ((k & 1) ? -x256 : x256);
        re *= SC;
        im *= SC;
        g_Yr[row][k] = re;
        g_Yi[row][k] = im;
        if (k == 0) {
            g_Yr[row][NN / 2] = SC * (x0 + x256 + pAlt[0] + pAlt[1] + pAlt[2] + pAlt[3]);
            g_Yi[row][NN / 2] = 0.0f;
        } else {
            g_Yr[row][NN - k] = re;
            g_Yi[row][NN - k] = -im;
        }
    }
}

// ---------------------------------------------------------------------------
// Kernel 2: Bx[k,l] = y[k]*conj(y[l])*y[(l-k) mod N], summed over T.
// HERMITIAN HALVING: real input => Bx[N-k, (N-l)%N] = conj(Bx[k,l]) exactly,
// so only k=0..256 is computed (grid.x = 17) and rows 257..511 are emitted
// as mirrored stores (Re copied, Im negated, l reversed) from the same accs.
// Tile: 256 thr = 4 ksub x 64 l-lanes; thread tile 4k x 8l; XOR bank swizzle.
// ---------------------------------------------------------------------------
__global__ __launch_bounds__(256, 2) void bispec_kernel(float* __restrict__ out) {
    __shared__ float ysr[TT][NN];
    __shared__ float ysi[TT][NN];

    const int b    = blockIdx.y;     // 0..31
    const int kblk = blockIdx.x;     // 0..16 (16 k each; block 16 mostly idle stores)

    {
        const float4* srcr = (const float4*)g_Yr[b * TT];
        const float4* srci = (const float4*)g_Yi[b * TT];
        for (int i = threadIdx.x; i < TT * NN / 4; i += 256) {
            const int t = i >> 7;
            const int j = (i & 127) << 2;
            const int o = swz(j);
            *(float4*)&ysr[t][o] = srcr[i];
            *(float4*)&ysi[t][o] = srci[i];
        }
    }
    __syncthreads();

    const int lane64 = threadIdx.x & 63;
    const int ksub   = threadIdx.x >> 6;       // warp-uniform
    const int k0     = kblk * 16 + ksub * 4;   // 4 consecutive k
    const int lbase  = lane64 * 8;             // 8 consecutive l

    u64 accr[4][4], acci[4][4];                // [ka][lpair]
#pragma unroll
    for (int a = 0; a < 4; ++a)
#pragma unroll
        for (int p = 0; p < 4; ++p) { accr[a][p] = 0ull; acci[a][p] = 0ull; }

#pragma unroll 1
    for (int t = 0; t < TT; ++t) {
        // y[l]: 8 consecutive floats, 2 float4 per component (swizzled, CF)
        const float4 l0r = *(const float4*)&ysr[t][swz(lbase)];
        const float4 l1r = *(const float4*)&ysr[t][swz(lbase + 4)];
        const float4 l0i = *(const float4*)&ysi[t][swz(lbase)];
        const float4 l1i = *(const float4*)&ysi[t][swz(lbase + 4)];
        const u64 ylr[4] = { pk2(l0r.x,l0r.y), pk2(l0r.z,l0r.w),
                             pk2(l1r.x,l1r.y), pk2(l1r.z,l1r.w) };
        const u64 yli[4] = { pk2(l0i.x,l0i.y), pk2(l0i.z,l0i.w),
                             pk2(l1i.x,l1i.y), pk2(l1i.z,l1i.w) };

        // yc window: 12 consecutive values starting at lbase-k0-4 (mod 512)
        const int base = (lbase - k0 - 4 + 1024) & (NN - 1);
        const int A0 = swz(base);
        const int A1 = swz((base + 4) & (NN - 1));
        const int A2 = swz((base + 8) & (NN - 1));
        const float4 c0r = *(const float4*)&ysr[t][A0];
        const float4 c1r = *(const float4*)&ysr[t][A1];
        const float4 c2r = *(const float4*)&ysr[t][A2];
        const float4 c0i = *(const float4*)&ysi[t][A0];
        const float4 c1i = *(const float4*)&ysi[t][A1];
        const float4 c2i = *(const float4*)&ysi[t][A2];
        // even-offset pairs (offsets 0,2,4,6,8,10)
        const u64 evr[6] = { pk2(c0r.x,c0r.y), pk2(c0r.z,c0r.w),
                             pk2(c1r.x,c1r.y), pk2(c1r.z,c1r.w),
                             pk2(c2r.x,c2r.y), pk2(c2r.z,c2r.w) };
        const u64 evi[6] = { pk2(c0i.x,c0i.y), pk2(c0i.z,c0i.w),
                             pk2(c1i.x,c1i.y), pk2(c1i.z,c1i.w),
                             pk2(c2i.x,c2i.y), pk2(c2i.z,c2i.w) };
        // odd-offset pairs (offsets 1,3,5,7,9)
        const u64 odr[5] = { pk2(c0r.y,c0r.z), pk2(c0r.w,c1r.x),
                             pk2(c1r.y,c1r.z), pk2(c1r.w,c2r.x),
                             pk2(c2r.y,c2r.z) };
        const u64 odi[5] = { pk2(c0i.y,c0i.z), pk2(c0i.w,c1i.x),
                             pk2(c1i.y,c1i.z), pk2(c1i.w,c2i.x),
                             pk2(c2i.y,c2i.z) };

        // y[k]: one broadcast float4 per component (k0 4-aligned, warp-uniform)
        const float4 kr4 = *(const float4*)&ysr[t][swz(k0 & (NN - 1))];
        const float4 ki4 = *(const float4*)&ysi[t][swz(k0 & (NN - 1))];
        const float krA[4] = { kr4.x, kr4.y, kr4.z, kr4.w };
        const float kiA[4] = { ki4.x, ki4.y, ki4.z, ki4.w };

#pragma unroll
        for (int ka = 0; ka < 4; ++ka) {
            const u64 ykr2  = pk2(krA[ka], krA[ka]);
            const u64 yki2  = pk2(kiA[ka], kiA[ka]);
            const u64 nykr2 = ykr2 ^ SGNMASK;
#pragma unroll
            for (int lp = 0; lp < 4; ++lp) {
                const int o = 4 + 2 * lp - ka;          // 1..10, compile-time
                const u64 ycr2 = (o & 1) ? odr[(o - 1) >> 1] : evr[o >> 1];
                const u64 yci2 = (o & 1) ? odi[(o - 1) >> 1] : evi[o >> 1];
                const u64 ar2  = f2fma(yki2, yli[lp], f2mul(ykr2, ylr[lp]));
                const u64 ai2  = f2fma(nykr2, yli[lp], f2mul(yki2, ylr[lp]));
                const u64 nai2 = ai2 ^ SGNMASK;
                accr[ka][lp] = f2fma(ar2,  ycr2, accr[ka][lp]);
                accr[ka][lp] = f2fma(nai2, yci2, accr[ka][lp]);
                acci[ka][lp] = f2fma(ar2,  yci2, acci[ka][lp]);
                acci[ka][lp] = f2fma(ai2,  ycr2, acci[ka][lp]);
            }
        }
    }

    float* outb = out + (size_t)b * 2 * NN * NN;
#pragma unroll
    for (int ka = 0; ka < 4; ++ka) {
        const int k = k0 + ka;
        float r[8], im_[8];
        up2(accr[ka][0], r[0], r[1]);   up2(accr[ka][1], r[2], r[3]);
        up2(accr[ka][2], r[4], r[5]);   up2(accr[ka][3], r[6], r[7]);
        up2(acci[ka][0], im_[0], im_[1]); up2(acci[ka][1], im_[2], im_[3]);
        up2(acci[ka][2], im_[4], im_[5]); up2(acci[ka][3], im_[6], im_[7]);

        if (k <= NN / 2) {   // normal rows 0..256
            float* rowr = outb + (size_t)k * NN + lbase;
            float* rowi = rowr + (size_t)NN * NN;
            *(float4*)(rowr)     = make_float4(r[0], r[1], r[2], r[3]);
            *(float4*)(rowr + 4) = make_float4(r[4], r[5], r[6], r[7]);
            *(float4*)(rowi)     = make_float4(im_[0], im_[1], im_[2], im_[3]);
            *(float4*)(rowi + 4) = make_float4(im_[4], im_[5], im_[6], im_[7]);
        }
        if (k >= 1 && k <= NN / 2 - 1) {   // mirror rows 511..257 (exact conj)
            const int km = NN - k;
            float* mrowr = outb + (size_t)km * NN;
            float* mrowi = mrowr + (size_t)NN * NN;
#pragma unroll
            for (int j = 0; j < 8; ++j) {
                const int col = (NN - (lbase + j)) & (NN - 1);
                mrowr[col] = r[j];
                mrowi[col] = -im_[j];
            }
        }
    }
}

extern "C" void kernel_launch(void* const* d_in, const int* in_sizes, int n_in,
                              void* d_out, int out_size) {
    const float* target = (const float*)d_in[0];
    float* out = (float*)d_out;

    dft512_kernel<<<NROWS, 1024>>>(target);

    dim3 grid(17, BATCH);   // k = 0..271 computed; rows 257..511 via mirror
    bispec_kernel<<<grid, 256>>>(out);

    if ((size_t)out_size >= SRC_ELEMS + TGT_ELEMS) {
        cudaMemcpyAsync(out + SRC_ELEMS, target, TGT_ELEMS * sizeof(float),
                        cudaMemcpyDeviceToDevice, 0);
    }
}

// round 17
// speedup vs baseline: 1.4645x; 1.4645x over previous
#include <cuda_runtime.h>
#include <cuda_bf16.h>

#define NN 512
#define BATCH 32
#define TT 4
#define NROWS (BATCH * TT)                        // 128
#define SRC_ELEMS ((size_t)BATCH * 2 * NN * NN)   // 16,777,216
#define TGT_ELEMS ((size_t)NROWS * NN)            // 65,536

// FFT results (pre-scaled by cbrt(0.25)), SoA. Allocation-free scratch.
__device__ float g_Yr[NROWS][NN];
__device__ float g_Yi[NROWS][NN];

typedef unsigned long long u64;

// ---- packed f32x2 helpers ----
__device__ __forceinline__ u64 pk2(float lo, float hi) {
    u64 r; asm("mov.b64 %0, {%1, %2};" : "=l"(r) : "f"(lo), "f"(hi)); return r;
}
__device__ __forceinline__ void up2(u64 v, float& lo, float& hi) {
    asm("mov.b64 {%0, %1}, %2;" : "=f"(lo), "=f"(hi) : "l"(v));
}
__device__ __forceinline__ u64 f2mul(u64 a, u64 b) {
    u64 d; asm("mul.rn.f32x2 %0, %1, %2;" : "=l"(d) : "l"(a), "l"(b)); return d;
}
__device__ __forceinline__ u64 f2fma(u64 a, u64 b, u64 c) {
    u64 d; asm("fma.rn.f32x2 %0, %1, %2, %3;" : "=l"(d) : "l"(a), "l"(b), "l"(c)); return d;
}

#define SGNMASK 0x8000000080000000ULL

// bank swizzle (bijective): j -> j XOR (4 * ((j>>5)&1)).
__device__ __forceinline__ int swz(int j) { return j ^ ((j >> 3) & 4); }

// transpose layout for the mirror-reversal staging buffer: conflict-free for
// both "thread owns cols 8l+j" writes and "thread needs cols (512-8l'-j)%512"
// reads (col&7 is lane-uniform per phase; col>>3 is lane-stride ±1).
__device__ __forceinline__ int tr(int col) { return (col & 7) * 64 + (col >> 3); }

// ---------------------------------------------------------------------------
// Kernel 1: 512-pt DFT of real input, per row (b,t). Output pre-scaled by
// cbrt(0.25) so the bispectrum triple product carries 1/T = 0.25 exactly.
// ---------------------------------------------------------------------------
__global__ __launch_bounds__(1024) void dft512_kernel(const float* __restrict__ x) {
    __shared__ float xs[NN];
    __shared__ float s[NN / 2];
    __shared__ float d[NN / 2];
    __shared__ float pRe[3][256];
    __shared__ float pIm[3][256];
    __shared__ float pAlt[4];

    const int row = blockIdx.x;
    const int tid = threadIdx.x;
    const int k   = tid & 255;
    const int q   = tid >> 8;

    if (tid < NN) xs[tid] = x[row * NN + tid];
    __syncthreads();
    if (tid >= 1 && tid < 256) {
        s[tid] = xs[tid] + xs[NN - tid];
        d[tid] = xs[tid] - xs[NN - tid];
    }
    __syncthreads();

    const float W = 6.283185307179586f / (float)NN;
    float s2, c2;
    sincosf(2.0f * W * (float)k, &s2, &c2);

    float re = 0.0f, im = 0.0f, alt = 0.0f;

#pragma unroll
    for (int c = 0; c < 2; ++c) {
        const int n0  = q * 64 + c * 32;
        const int phA = (k * n0) & (NN - 1);
        const int phB = (k * (n0 + 1)) & (NN - 1);
        float sA, cA, sB, cB;
        sincosf(W * (float)phA, &sA, &cA);
        sincosf(W * (float)phB, &sB, &cB);
#pragma unroll
        for (int j = 0; j < 16; ++j) {
            const int nA = n0 + 2 * j;
            const int nB = nA + 1;
            if (nA >= 1) {
                re  = fmaf(s[nA], cA, re);
                im  = fmaf(-d[nA], sA, im);
                alt += s[nA];
            }
            re  = fmaf(s[nB], cB, re);
            im  = fmaf(-d[nB], sB, im);
            alt -= s[nB];
            const float nrA = fmaf(cA, c2, -(sA * s2));
            sA = fmaf(cA, s2, sA * c2); cA = nrA;
            const float nrB = fmaf(cB, c2, -(sB * s2));
            sB = fmaf(cB, s2, sB * c2); cB = nrB;
        }
    }

    if (q > 0) {
        pRe[q - 1][k] = re;
        pIm[q - 1][k] = im;
        if (k == 0) pAlt[q] = alt;
    } else if (k == 0) {
        pAlt[0] = alt;
    }
    __syncthreads();

    if (q == 0) {
        const float SC = 0.6299605249474366f;   // cbrt(0.25)
        re += pRe[0][k] + pRe[1][k] + pRe[2][k];
        im += pIm[0][k] + pIm[1][k] + pIm[2][k];
        const float x0 = xs[0], x256 = xs[NN / 2];
        re += x0 + ((k & 1) ? -x256 : x256);
        re *= SC;
        im *= SC;
        g_Yr[row][k] = re;
        g_Yi[row][k] = im;
        if (k == 0) {
            g_Yr[row][NN / 2] = SC * (x0 + x256 + pAlt[0] + pAlt[1] + pAlt[2] + pAlt[3]);
            g_Yi[row][NN / 2] = 0.0f;
        } else {
            g_Yr[row][NN - k] = re;
            g_Yi[row][NN - k] = -im;
        }
    }
}

// ---------------------------------------------------------------------------
// Kernel 2: Bx[k,l] = y[k]*conj(y[l])*y[(l-k) mod N], summed over T.
// Hermitian halving: only k=0..271 computed (grid.x=17); rows 257..511 are
// conj-mirrors emitted through a conflict-free smem transpose so that the
// reversed-l mirror rows still go out as coalesced float4 stores.
// ---------------------------------------------------------------------------
__global__ __launch_bounds__(256, 2) void bispec_kernel(float* __restrict__ out) {
    __shared__ float ysr[TT][NN];
    __shared__ float ysi[TT][NN];
    __shared__ float mbuf[4][2][NN];   // [ksub][re/im][transposed col]

    const int b    = blockIdx.y;     // 0..31
    const int kblk = blockIdx.x;     // 0..16

    {
        const float4* srcr = (const float4*)g_Yr[b * TT];
        const float4* srci = (const float4*)g_Yi[b * TT];
        for (int i = threadIdx.x; i < TT * NN / 4; i += 256) {
            const int t = i >> 7;
            const int j = (i & 127) << 2;
            const int o = swz(j);
            *(float4*)&ysr[t][o] = srcr[i];
            *(float4*)&ysi[t][o] = srci[i];
        }
    }
    __syncthreads();

    const int lane64 = threadIdx.x & 63;
    const int ksub   = threadIdx.x >> 6;       // warp-uniform
    const int k0     = kblk * 16 + ksub * 4;   // 4 consecutive k
    const int lbase  = lane64 * 8;             // 8 consecutive l

    u64 accr[4][4], acci[4][4];                // [ka][lpair]
#pragma unroll
    for (int a = 0; a < 4; ++a)
#pragma unroll
        for (int p = 0; p < 4; ++p) { accr[a][p] = 0ull; acci[a][p] = 0ull; }

#pragma unroll 1
    for (int t = 0; t < TT; ++t) {
        const float4 l0r = *(const float4*)&ysr[t][swz(lbase)];
        const float4 l1r = *(const float4*)&ysr[t][swz(lbase + 4)];
        const float4 l0i = *(const float4*)&ysi[t][swz(lbase)];
        const float4 l1i = *(const float4*)&ysi[t][swz(lbase + 4)];
        const u64 ylr[4] = { pk2(l0r.x,l0r.y), pk2(l0r.z,l0r.w),
                             pk2(l1r.x,l1r.y), pk2(l1r.z,l1r.w) };
        const u64 yli[4] = { pk2(l0i.x,l0i.y), pk2(l0i.z,l0i.w),
                             pk2(l1i.x,l1i.y), pk2(l1i.z,l1i.w) };

        const int base = (lbase - k0 - 4 + 1024) & (NN - 1);
        const int A0 = swz(base);
        const int A1 = swz((base + 4) & (NN - 1));
        const int A2 = swz((base + 8) & (NN - 1));
        const float4 c0r = *(const float4*)&ysr[t][A0];
        const float4 c1r = *(const float4*)&ysr[t][A1];
        const float4 c2r = *(const float4*)&ysr[t][A2];
        const float4 c0i = *(const float4*)&ysi[t][A0];
        const float4 c1i = *(const float4*)&ysi[t][A1];
        const float4 c2i = *(const float4*)&ysi[t][A2];
        const u64 evr[6] = { pk2(c0r.x,c0r.y), pk2(c0r.z,c0r.w),
                             pk2(c1r.x,c1r.y), pk2(c1r.z,c1r.w),
                             pk2(c2r.x,c2r.y), pk2(c2r.z,c2r.w) };
        const u64 evi[6] = { pk2(c0i.x,c0i.y), pk2(c0i.z,c0i.w),
                             pk2(c1i.x,c1i.y), pk2(c1i.z,c1i.w),
                             pk2(c2i.x,c2i.y), pk2(c2i.z,c2i.w) };
        const u64 odr[5] = { pk2(c0r.y,c0r.z), pk2(c0r.w,c1r.x),
                             pk2(c1r.y,c1r.z), pk2(c1r.w,c2r.x),
                             pk2(c2r.y,c2r.z) };
        const u64 odi[5] = { pk2(c0i.y,c0i.z), pk2(c0i.w,c1i.x),
                             pk2(c1i.y,c1i.z), pk2(c1i.w,c2i.x),
                             pk2(c2i.y,c2i.z) };

        const float4 kr4 = *(const float4*)&ysr[t][swz(k0 & (NN - 1))];
        const float4 ki4 = *(const float4*)&ysi[t][swz(k0 & (NN - 1))];
        const float krA[4] = { kr4.x, kr4.y, kr4.z, kr4.w };
        const float kiA[4] = { ki4.x, ki4.y, ki4.z, ki4.w };

#pragma unroll
        for (int ka = 0; ka < 4; ++ka) {
            const u64 ykr2  = pk2(krA[ka], krA[ka]);
            const u64 yki2  = pk2(kiA[ka], kiA[ka]);
            const u64 nykr2 = ykr2 ^ SGNMASK;
#pragma unroll
            for (int lp = 0; lp < 4; ++lp) {
                const int o = 4 + 2 * lp - ka;          // 1..10, compile-time
                const u64 ycr2 = (o & 1) ? odr[(o - 1) >> 1] : evr[o >> 1];
                const u64 yci2 = (o & 1) ? odi[(o - 1) >> 1] : evi[o >> 1];
                const u64 ar2  = f2fma(yki2, yli[lp], f2mul(ykr2, ylr[lp]));
                const u64 ai2  = f2fma(nykr2, yli[lp], f2mul(yki2, ylr[lp]));
                const u64 nai2 = ai2 ^ SGNMASK;
                accr[ka][lp] = f2fma(ar2,  ycr2, accr[ka][lp]);
                accr[ka][lp] = f2fma(nai2, yci2, accr[ka][lp]);
                acci[ka][lp] = f2fma(ar2,  yci2, acci[ka][lp]);
                acci[ka][lp] = f2fma(ai2,  ycr2, acci[ka][lp]);
            }
        }
    }

    float* outb = out + (size_t)b * 2 * NN * NN;
    const bool hasMirror = (kblk != 16);       // block-uniform

#pragma unroll 1
    for (int ka = 0; ka < 4; ++ka) {
        const int k = k0 + ka;
        float r[8], im_[8];
        up2(accr[ka][0], r[0], r[1]);     up2(accr[ka][1], r[2], r[3]);
        up2(accr[ka][2], r[4], r[5]);     up2(accr[ka][3], r[6], r[7]);
        up2(acci[ka][0], im_[0], im_[1]); up2(acci[ka][1], im_[2], im_[3]);
        up2(acci[ka][2], im_[4], im_[5]); up2(acci[ka][3], im_[6], im_[7]);

        if (k <= NN / 2) {   // normal rows 0..256, coalesced float4
            float* rowr = outb + (size_t)k * NN + lbase;
            float* rowi = rowr + (size_t)NN * NN;
            *(float4*)(rowr)     = make_float4(r[0], r[1], r[2], r[3]);
            *(float4*)(rowr + 4) = make_float4(r[4], r[5], r[6], r[7]);
            *(float4*)(rowi)     = make_float4(im_[0], im_[1], im_[2], im_[3]);
            *(float4*)(rowi + 4) = make_float4(im_[4], im_[5], im_[6], im_[7]);
        }

        if (hasMirror) {     // rows 511..257 = conj with l reversed (exact)
            __syncthreads();                       // mbuf reuse across ka
            if (k >= 1 && k <= NN / 2 - 1) {
#pragma unroll
                for (int j = 0; j < 8; ++j) {
                    const int A = tr(lbase + j);   // conflict-free write
                    mbuf[ksub][0][A] = r[j];
                    mbuf[ksub][1][A] = -im_[j];
                }
            }
            __syncthreads();
            if (k >= 1 && k <= NN / 2 - 1) {
                const int km = NN - k;
                float mr[8], mi[8];
#pragma unroll
                for (int j = 0; j < 8; ++j) {      // conflict-free read
                    const int col = (NN - (lbase + j)) & (NN - 1);
                    const int A = tr(col);
                    mr[j] = mbuf[ksub][0][A];
                    mi[j] = mbuf[ksub][1][A];
                }
                float* mrowr = outb + (size_t)km * NN + lbase;
                float* mrowi = mrowr + (size_t)NN * NN;
                *(float4*)(mrowr)     = make_float4(mr[0], mr[1], mr[2], mr[3]);
                *(float4*)(mrowr + 4) = make_float4(mr[4], mr[5], mr[6], mr[7]);
                *(float4*)(mrowi)     = make_float4(mi[0], mi[1], mi[2], mi[3]);
                *(float4*)(mrowi + 4) = make_float4(mi[4], mi[5], mi[6], mi[7]);
            }
        }
    }
}

extern "C" void kernel_launch(void* const* d_in, const int* in_sizes, int n_in,
                              void* d_out, int out_size) {
    const float* target = (const float*)d_in[0];
    float* out = (float*)d_out;

    dft512_kernel<<<NROWS, 1024>>>(target);

    dim3 grid(17, BATCH);   // k = 0..271 computed; rows 257..511 via mirror
    bispec_kernel<<<grid, 256>>>(out);

    if ((size_t)out_size >= SRC_ELEMS + TGT_ELEMS) {
        cudaMemcpyAsync(out + SRC_ELEMS, target, TGT_ELEMS * sizeof(float),
                        cudaMemcpyDeviceToDevice, 0);
    }
}